// round 7
// baseline (speedup 1.0000x reference)
#include <cuda_runtime.h>
#include <cuda_fp16.h>
#include <cstdint>

// FP4(E2M1) weight-only linear, single-pass fp16 mma.sync, scales folded into
// fp16 A registers via pre-packed per-warp scale fragments.
// out[32,8192] = inp[32,8192] @ W[8192,8192]^T + bias
// W[n,k] = LUT(nib) * scales[n,k/16] * amax (amax folded into activations)

#define TOKENS   32
#define NFEAT    8192
#define KFEAT    8192
#define NWIN     (KFEAT / 16)          // 512 mma k-steps
#define NMP      (NWIN / 2)            // 256 window-pairs
#define KSPLIT   8
#define MP_PER_CTA  (NMP / KSPLIT)     // 32
#define NBLK     (NFEAT / 32)          // 256 warp row-blocks

__device__ uint4 g_bfrag[NMP * 4 * 32];             // [mp][g][lane] fp16x2 x4 (2 MB)
__device__ uint2 g_spk[NBLK * NMP * 16];            // packed fp16 scales (8 MB)
__device__ float g_part[KSPLIT * TOKENS * NFEAT];   // split-K partials (8 MB)

// decode packed byte -> fp16x2 {lut[hi nib] | lut[lo nib]} (exact, unscaled)
__device__ __forceinline__ uint32_t dec16(uint32_t b){
    uint32_t h = __byte_perm(0x3E3C3800u, 0x46444240u, b & 0x77u);
    uint32_t r = __byte_perm(h, 0u, 0x1404u);
    return r | ((b & 0x8u) << 12) | ((b & 0x80u) << 24);
}
__device__ __forceinline__ uint32_t hmul2(uint32_t a, uint32_t b){
    uint32_t r;
    asm("mul.rn.f16x2 %0, %1, %2;" : "=r"(r) : "r"(a), "r"(b));
    return r;
}
__device__ __forceinline__ uint32_t pack_f16x2(float lo, float hi){
    uint32_t r;
    asm("cvt.rn.f16x2.f32 %0, %1, %2;" : "=r"(r) : "f"(hi), "f"(lo));
    return r;
}
__device__ __forceinline__ void mma_acc(
    float& d0, float& d1, float& d2, float& d3,
    uint32_t a0, uint32_t a1, uint32_t a2, uint32_t a3,
    uint32_t b0, uint32_t b1)
{
    asm("mma.sync.aligned.m16n8k16.row.col.f32.f16.f16.f32 "
        "{%0,%1,%2,%3}, {%4,%5,%6,%7}, {%8,%9}, {%0,%1,%2,%3};"
        : "+f"(d0), "+f"(d1), "+f"(d2), "+f"(d3)
        : "r"(a0), "r"(a1), "r"(a2), "r"(a3), "r"(b0), "r"(b1));
}

// ---------------- fused prologue ----------------
// All threads: build one g_spk entry. First 32768 threads: also build g_bfrag.
// spk entry (nb, mp, idx): idx = 2*r + p, r=0..7, p=0..1.
//   x = f16(scales[nb*32+r   ][2mp+p]) | f16(scales[nb*32+r+ 8][2mp+p])<<16
//   y = f16(scales[nb*32+r+16][2mp+p]) | f16(scales[nb*32+r+24][2mp+p])<<16
__global__ void prologue_kernel(const float* __restrict__ inp,
                                const float* __restrict__ scales,
                                const float* __restrict__ amax)
{
    int t = blockIdx.x * blockDim.x + threadIdx.x;   // 0 .. 1048575

    {   // scale packing
        int nb  = t >> 12;            // 4096 entries per nb
        int rem = t & 4095;
        int mp  = rem >> 4;
        int idx = rem & 15;
        int r   = idx >> 1;
        int p   = idx & 1;
        int col = 2 * mp + p;
        int row = nb * 32 + r;
        float s0 = __ldg(scales + (size_t)(row     ) * NWIN + col);
        float s1 = __ldg(scales + (size_t)(row +  8) * NWIN + col);
        float s2 = __ldg(scales + (size_t)(row + 16) * NWIN + col);
        float s3 = __ldg(scales + (size_t)(row + 24) * NWIN + col);
        g_spk[t] = make_uint2(pack_f16x2(s0, s1), pack_f16x2(s2, s3));
    }

    if (t < NMP * 4 * 32){   // bfrag
        int lane = t & 31;
        int g    = (t >> 5) & 3;
        int mp   = t >> 7;
        int c    = lane & 3;
        int n    = g * 8 + (lane >> 2);
        int k0   = 32 * mp + 8 * c;
        const float am = __ldg(amax);
        float4 a = *reinterpret_cast<const float4*>(inp + (size_t)n * KFEAT + k0);
        float4 b = *reinterpret_cast<const float4*>(inp + (size_t)n * KFEAT + k0 + 4);
        g_bfrag[t] = make_uint4(pack_f16x2(a.x * am, a.y * am),
                                pack_f16x2(a.z * am, a.w * am),
                                pack_f16x2(b.x * am, b.y * am),
                                pack_f16x2(b.z * am, b.w * am));
    }
}

// ---------------- main GEMM ----------------
// CTA: 128 thr = 4 warps; warp = 32 weight rows x 32 tokens.
// grid = (64, KSPLIT=8) = 512 CTAs, occ 4.
__global__ void __launch_bounds__(128, 4) fp4_hmma_kernel(
    const int* __restrict__ qw)        // [N, K/2] one packed byte per int32
{
    const int tid = threadIdx.x, wid = tid >> 5, lane = tid & 31;
    const int c  = lane & 3;
    const int r0 = blockIdx.x * 128 + wid * 32 + (lane >> 2);   // rows r0,+8,+16,+24
    const int mpb = blockIdx.y * MP_PER_CTA;
    const int nb  = blockIdx.x * 4 + wid;
    const int sidx = (lane >> 1) & 15;

    float acc[4][8];
    #pragma unroll
    for (int g = 0; g < 4; ++g)
        #pragma unroll
        for (int j = 0; j < 8; ++j) acc[g][j] = 0.f;

    const uint4* qr0 = reinterpret_cast<const uint4*>(qw + (size_t)(r0     ) * (KFEAT / 2)) + c;
    const uint4* qr1 = reinterpret_cast<const uint4*>(qw + (size_t)(r0 +  8) * (KFEAT / 2)) + c;
    const uint4* qr2 = reinterpret_cast<const uint4*>(qw + (size_t)(r0 + 16) * (KFEAT / 2)) + c;
    const uint4* qr3 = reinterpret_cast<const uint4*>(qw + (size_t)(r0 + 24) * (KFEAT / 2)) + c;
    const uint2* spkp = g_spk + ((size_t)nb * NMP << 4) + sidx;

    #pragma unroll 4
    for (int mpl = 0; mpl < MP_PER_CTA; ++mpl){
        const int mp = mpb + mpl;

        const uint4 q0 = __ldg(qr0 + mp * 4);
        const uint4 q1 = __ldg(qr1 + mp * 4);
        const uint4 q2 = __ldg(qr2 + mp * 4);
        const uint4 q3 = __ldg(qr3 + mp * 4);

        const uint2 sv = __ldg(spkp + (mp << 4));
        const uint32_t h0 = __byte_perm(sv.x, sv.x, 0x1010);   // dup f16 for rows r0
        const uint32_t h1 = __byte_perm(sv.x, sv.x, 0x3232);   // r0+8
        const uint32_t h2 = __byte_perm(sv.y, sv.y, 0x1010);   // r0+16
        const uint32_t h3 = __byte_perm(sv.y, sv.y, 0x3232);   // r0+24

        uint4 bf[4];
        #pragma unroll
        for (int g = 0; g < 4; ++g)
            bf[g] = __ldg(&g_bfrag[(size_t)(mp * 4 + g) * 32 + lane]);

        // ---- e = 0 (k 0..15 of pair) ----
        {
            const uint32_t a00 = hmul2(dec16(q0.x), h0), a02 = hmul2(dec16(q0.y), h0);
            const uint32_t a01 = hmul2(dec16(q1.x), h1), a03 = hmul2(dec16(q1.y), h1);
            const uint32_t a10 = hmul2(dec16(q2.x), h2), a12 = hmul2(dec16(q2.y), h2);
            const uint32_t a11 = hmul2(dec16(q3.x), h3), a13 = hmul2(dec16(q3.y), h3);
            #pragma unroll
            for (int g = 0; g < 4; ++g){
                mma_acc(acc[g][0], acc[g][1], acc[g][2], acc[g][3],
                        a00, a01, a02, a03, bf[g].x, bf[g].y);
                mma_acc(acc[g][4], acc[g][5], acc[g][6], acc[g][7],
                        a10, a11, a12, a13, bf[g].x, bf[g].y);
            }
        }
        // ---- e = 1 (k 16..31 of pair) ----
        {
            const uint32_t a00 = hmul2(dec16(q0.z), h0), a02 = hmul2(dec16(q0.w), h0);
            const uint32_t a01 = hmul2(dec16(q1.z), h1), a03 = hmul2(dec16(q1.w), h1);
            const uint32_t a10 = hmul2(dec16(q2.z), h2), a12 = hmul2(dec16(q2.w), h2);
            const uint32_t a11 = hmul2(dec16(q3.z), h3), a13 = hmul2(dec16(q3.w), h3);
            #pragma unroll
            for (int g = 0; g < 4; ++g){
                mma_acc(acc[g][0], acc[g][1], acc[g][2], acc[g][3],
                        a00, a01, a02, a03, bf[g].z, bf[g].w);
                mma_acc(acc[g][4], acc[g][5], acc[g][6], acc[g][7],
                        a10, a11, a12, a13, bf[g].z, bf[g].w);
            }
        }
    }

    // epilogue: token cols g*8+2c, 2c+1 ; rows r0, +8, +16, +24
    float* base = g_part + (size_t)blockIdx.y * (TOKENS * NFEAT);
    #pragma unroll
    for (int g = 0; g < 4; ++g){
        const int t0c = g * 8 + 2 * c;
        base[(size_t)t0c       * NFEAT + r0     ] = acc[g][0];
        base[(size_t)(t0c + 1) * NFEAT + r0     ] = acc[g][1];
        base[(size_t)t0c       * NFEAT + r0 +  8] = acc[g][2];
        base[(size_t)(t0c + 1) * NFEAT + r0 +  8] = acc[g][3];
        base[(size_t)t0c       * NFEAT + r0 + 16] = acc[g][4];
        base[(size_t)(t0c + 1) * NFEAT + r0 + 16] = acc[g][5];
        base[(size_t)t0c       * NFEAT + r0 + 24] = acc[g][6];
        base[(size_t)(t0c + 1) * NFEAT + r0 + 24] = acc[g][7];
    }
}

// ---------------- reduce split-K + bias (vectorized) ----------------
__global__ void reduce_kernel(const float* __restrict__ bias, float* __restrict__ out){
    int i4 = blockIdx.x * blockDim.x + threadIdx.x;
    if (i4 >= (TOKENS * NFEAT) / 4) return;
    const float4 b = *reinterpret_cast<const float4*>(bias + ((i4 * 4) & (NFEAT - 1)));
    float4 s = b;
    #pragma unroll
    for (int cp = 0; cp < KSPLIT; ++cp){
        const float4 v = *reinterpret_cast<const float4*>(g_part + (size_t)cp * (TOKENS * NFEAT) + i4 * 4);
        s.x += v.x; s.y += v.y; s.z += v.z; s.w += v.w;
    }
    reinterpret_cast<float4*>(out)[i4] = s;
}

extern "C" void kernel_launch(void* const* d_in, const int* in_sizes, int n_in,
                              void* d_out, int out_size)
{
    const float* inp    = (const float*)d_in[0];
    const int*   qw     = (const int*)  d_in[1];
    const float* scales = (const float*)d_in[2];
    const float* amax   = (const float*)d_in[3];
    const float* bias   = (const float*)d_in[4];
    float* out = (float*)d_out;

    prologue_kernel<<<(NBLK * NMP * 16) / 256, 256>>>(inp, scales, amax);

    dim3 grid(NFEAT / 128, KSPLIT);
    fp4_hmma_kernel<<<grid, 128>>>(qw);

    reduce_kernel<<<(TOKENS * NFEAT / 4 + 255) / 256, 256>>>(bias, out);
}